// round 1
// baseline (speedup 1.0000x reference)
#include <cuda_runtime.h>
#include <math.h>

#define NH    8
#define FOUT  512
#define NQ    4
#define CIN   256
#define HD    64
#define BB    4
#define SS    32768
#define RR    32          // NH * NQ score rows
#define LN_EPS 1e-5f
#define SCALE 0.125f      // HD^-0.5

#define D_CHUNKS 64
#define CHUNK_S  (SS / D_CHUNKS)  // 512
#define TILE_S   32

// ---------------- scratch (device globals; no allocations) ----------------
__device__ __align__(16) float gA[CIN * RR];                 // A_t[c][r], scaled
__device__ __align__(16) float gSb[RR];                      // scaled score bias
__device__ __align__(16) float gScores[(size_t)BB * RR * SS]; // 16 MB
__device__ __align__(16) float gM[BB * RR];
__device__ __align__(16) float gL[BB * RR];
__device__ __align__(16) float gPpart[(size_t)BB * D_CHUNKS * RR * CIN]; // 8 MB
__device__ __align__(16) float gMulti[BB * NQ * FOUT];

// ---------------- Kernel A: fold queries into Wk ----------------
// A[r=h*4+q][c] = scale * sum_d queries[q, h*64+d] * Wk[h*64+d, c]
// stored transposed: gA[c*32 + r]
__global__ void kA(const float* __restrict__ queries,
                   const float* __restrict__ Wk,
                   const float* __restrict__ bk) {
    int r = blockIdx.x;          // 0..31
    int h = r >> 2, q = r & 3;
    int c = threadIdx.x;         // 0..255
    const float* qrow = queries + q * FOUT + h * HD;
    float s = 0.f;
#pragma unroll 8
    for (int d = 0; d < HD; d++)
        s += qrow[d] * Wk[(size_t)(h * HD + d) * CIN + c];
    gA[c * RR + r] = s * SCALE;
    if (c == 0) {
        float sb = 0.f;
        for (int d = 0; d < HD; d++) sb += qrow[d] * bk[h * HD + d];
        gSb[r] = sb * SCALE;
    }
}

// ---------------- Kernel B: scores = A @ x  (M=32, K=256, N=S per batch) ----
// grid (S/256, B), block 256. thread (rg,cg): 8 rows x 4 cols (float4).
__global__ void __launch_bounds__(256) kB(const float* __restrict__ x) {
    __shared__ __align__(16) float sA[CIN * RR];  // 32 KB, rows of 32 floats
    int tid = threadIdx.x;
    int b = blockIdx.y;
    for (int i = tid; i < CIN * RR; i += 256) sA[i] = gA[i];
    __syncthreads();

    int rg = tid >> 6;          // 0..3 -> rows rg*8..rg*8+7
    int cg = tid & 63;          // 0..63 -> 4 s-columns
    int s0 = blockIdx.x * 256 + cg * 4;

    const float4* xp = (const float4*)(x + (size_t)b * CIN * SS + s0);
    float4 acc[8];
#pragma unroll
    for (int i = 0; i < 8; i++) acc[i] = make_float4(0.f, 0.f, 0.f, 0.f);

#pragma unroll 4
    for (int c = 0; c < CIN; c++) {
        float4 xv = xp[(size_t)c * (SS / 4)];
        const float4* ar = (const float4*)&sA[c * RR + rg * 8];
        float4 a0 = ar[0], a1 = ar[1];
        float a[8] = {a0.x, a0.y, a0.z, a0.w, a1.x, a1.y, a1.z, a1.w};
#pragma unroll
        for (int i = 0; i < 8; i++) {
            acc[i].x += a[i] * xv.x;
            acc[i].y += a[i] * xv.y;
            acc[i].z += a[i] * xv.z;
            acc[i].w += a[i] * xv.w;
        }
    }
#pragma unroll
    for (int i = 0; i < 8; i++) {
        int r = rg * 8 + i;
        float sb = gSb[r];
        float4 o = make_float4(acc[i].x + sb, acc[i].y + sb,
                               acc[i].z + sb, acc[i].w + sb);
        *(float4*)&gScores[((size_t)(b * RR + r)) * SS + s0] = o;
    }
}

// ---------------- Kernel C: per-row max & sum-exp (128 rows) ----------------
__global__ void __launch_bounds__(256) kC() {
    int row = blockIdx.x;  // 0..127
    const float4* p = (const float4*)(gScores + (size_t)row * SS);
    int tid = threadIdx.x, w = tid >> 5, lane = tid & 31;
    __shared__ float sred[8];

    float m = -1e30f;
    for (int i = tid; i < SS / 4; i += 256) {
        float4 v = p[i];
        m = fmaxf(m, fmaxf(fmaxf(v.x, v.y), fmaxf(v.z, v.w)));
    }
#pragma unroll
    for (int off = 16; off; off >>= 1) m = fmaxf(m, __shfl_xor_sync(~0u, m, off));
    if (lane == 0) sred[w] = m;
    __syncthreads();
    if (tid == 0) {
        float mm = sred[0];
        for (int i = 1; i < 8; i++) mm = fmaxf(mm, sred[i]);
        sred[0] = mm;
    }
    __syncthreads();
    m = sred[0];
    __syncthreads();

    float l = 0.f;
    for (int i = tid; i < SS / 4; i += 256) {
        float4 v = p[i];
        l += __expf(v.x - m) + __expf(v.y - m) + __expf(v.z - m) + __expf(v.w - m);
    }
#pragma unroll
    for (int off = 16; off; off >>= 1) l += __shfl_xor_sync(~0u, l, off);
    if (lane == 0) sred[w] = l;
    __syncthreads();
    if (tid == 0) {
        float s = 0.f;
        for (int i = 0; i < 8; i++) s += sred[i];
        gM[row] = m;
        gL[row] = s;
    }
}

// ---------------- Kernel D: P_part[b][chunk][r][c] = sum_s w[r,s]*x[c,s] -----
// grid (64 chunks, B), block 256. thread: 8 r x 4 c (c strided by 64).
__global__ void __launch_bounds__(256) kD(const float* __restrict__ x) {
    __shared__ float xs[CIN * 33];                     // x tile [c][s] pad 1
    __shared__ __align__(16) float ws[TILE_S * 36];    // w tile [s][r] pad to 36
    __shared__ float sm[RR];

    int chunk = blockIdx.x, b = blockIdx.y;
    int tid = threadIdx.x;
    int rg = tid >> 6, cg = tid & 63;
    if (tid < RR) sm[tid] = gM[b * RR + tid];

    float acc[8][4];
#pragma unroll
    for (int i = 0; i < 8; i++)
#pragma unroll
        for (int j = 0; j < 4; j++) acc[i][j] = 0.f;

    const float* xb = x + (size_t)b * CIN * SS;
    const float* scb = gScores + (size_t)b * RR * SS;
    int s_chunk0 = chunk * CHUNK_S;

    for (int t = 0; t < CHUNK_S / TILE_S; t++) {
        int sb = s_chunk0 + t * TILE_S;
        __syncthreads();
        // load x tile (coalesced; conflict-free STS due to 33-stride)
#pragma unroll 4
        for (int j = 0; j < 32; j++) {
            int lin = j * 256 + tid;
            int c = lin >> 5, s = lin & 31;
            xs[c * 33 + s] = xb[(size_t)c * SS + sb + s];
        }
        // load w tile = exp(score - m)
#pragma unroll
        for (int j = 0; j < 4; j++) {
            int lin = j * 256 + tid;
            int r = lin >> 5, s = lin & 31;
            ws[s * 36 + r] = __expf(scb[(size_t)r * SS + sb + s] - sm[r]);
        }
        __syncthreads();
#pragma unroll 4
        for (int s = 0; s < TILE_S; s++) {
            const float4* wp = (const float4*)&ws[s * 36 + rg * 8];
            float4 w0 = wp[0], w1 = wp[1];
            float wr[8] = {w0.x, w0.y, w0.z, w0.w, w1.x, w1.y, w1.z, w1.w};
            float xv[4];
#pragma unroll
            for (int j = 0; j < 4; j++) xv[j] = xs[(cg + 64 * j) * 33 + s];
#pragma unroll
            for (int i = 0; i < 8; i++)
#pragma unroll
                for (int j = 0; j < 4; j++) acc[i][j] += wr[i] * xv[j];
        }
    }
    // write partials (coalesced over cg)
#pragma unroll
    for (int i = 0; i < 8; i++) {
        size_t base = (((size_t)(b * D_CHUNKS + chunk)) * RR + (rg * 8 + i)) * CIN;
#pragma unroll
        for (int j = 0; j < 4; j++)
            gPpart[base + cg + 64 * j] = acc[i][j];
    }
}

// ---------------- Kernel E1: reduce partials, apply 1/l, fold Wv + bv -------
// grid (8 heads, B), block 256
__global__ void __launch_bounds__(256) kE1(const float* __restrict__ Wv,
                                           const float* __restrict__ bv) {
    __shared__ __align__(16) float sPn[4 * 260];  // Pn[q][c], padded row 260
    int h = blockIdx.x, b = blockIdx.y;
    int tid = threadIdx.x;

#pragma unroll
    for (int k = 0; k < 4; k++) {
        int o = k * 256 + tid;
        int q = o >> 8, c = o & 255;
        int r = h * 4 + q;
        const float* pp = gPpart + ((size_t)(b * D_CHUNKS) * RR + r) * CIN + c;
        float s = 0.f;
#pragma unroll 8
        for (int ch = 0; ch < D_CHUNKS; ch++) s += pp[(size_t)ch * RR * CIN];
        s *= (1.0f / gL[b * RR + r]);
        sPn[q * 260 + c] = s;
    }
    __syncthreads();

    int q = tid >> 6, d = tid & 63;
    const float4* wv = (const float4*)(Wv + (size_t)(h * HD + d) * CIN);
    const float4* pn = (const float4*)&sPn[q * 260];
    float sum = 0.f;
#pragma unroll 8
    for (int c4 = 0; c4 < CIN / 4; c4++) {
        float4 a = wv[c4];
        float4 p = pn[c4];
        sum += a.x * p.x + a.y * p.y + a.z * p.z + a.w * p.w;
    }
    sum += bv[h * HD + d];
    gMulti[b * (NQ * FOUT) + q * FOUT + h * HD + d] = sum;
}

// ---------------- Kernel E2: out = multi @ Wo^T + bo, then LayerNorm --------
// grid B, block 512 (== FOUT)
__global__ void __launch_bounds__(512) kE2(const float* __restrict__ Wo,
                                           const float* __restrict__ bo,
                                           const float* __restrict__ gamma,
                                           const float* __restrict__ beta,
                                           float* __restrict__ out) {
    __shared__ __align__(16) float sMulti[NQ * FOUT];  // 2048
    __shared__ float sOut[FOUT];
    __shared__ float r1[16], r2[16];
    int b = blockIdx.x;
    int tid = threadIdx.x, w = tid >> 5, lane = tid & 31;

    for (int i = tid; i < NQ * FOUT; i += 512) sMulti[i] = gMulti[b * (NQ * FOUT) + i];
    __syncthreads();

    const float4* sm4 = (const float4*)sMulti;
    for (int f = w; f < FOUT; f += 16) {
        const float4* wo = (const float4*)(Wo + (size_t)f * (NQ * FOUT));
        float sum = 0.f;
        for (int j = lane; j < (NQ * FOUT) / 4; j += 32) {
            float4 a = wo[j];
            float4 m = sm4[j];
            sum += a.x * m.x + a.y * m.y + a.z * m.z + a.w * m.w;
        }
#pragma unroll
        for (int off = 16; off; off >>= 1) sum += __shfl_xor_sync(~0u, sum, off);
        if (lane == 0) sOut[f] = sum + bo[f];
    }
    __syncthreads();

    float v = sOut[tid];
    float s1 = v, s2 = v * v;
#pragma unroll
    for (int off = 16; off; off >>= 1) {
        s1 += __shfl_xor_sync(~0u, s1, off);
        s2 += __shfl_xor_sync(~0u, s2, off);
    }
    if (lane == 0) { r1[w] = s1; r2[w] = s2; }
    __syncthreads();
    if (tid < 16) {
        s1 = r1[tid]; s2 = r2[tid];
#pragma unroll
        for (int off = 8; off; off >>= 1) {
            s1 += __shfl_xor_sync(0x0000ffffu, s1, off);
            s2 += __shfl_xor_sync(0x0000ffffu, s2, off);
        }
        if (tid == 0) {
            float mu = s1 / (float)FOUT;
            float var = s2 / (float)FOUT - mu * mu;
            r1[0] = mu;
            r2[0] = rsqrtf(var + LN_EPS);
        }
    }
    __syncthreads();
    float mu = r1[0], rstd = r2[0];
    out[b * FOUT + tid] = (v - mu) * rstd * gamma[tid] + beta[tid];
}

// ---------------- launch ----------------
extern "C" void kernel_launch(void* const* d_in, const int* in_sizes, int n_in,
                              void* d_out, int out_size) {
    (void)in_sizes; (void)n_in; (void)out_size;
    const float* x       = (const float*)d_in[0];
    const float* queries = (const float*)d_in[1];
    const float* Wk      = (const float*)d_in[2];
    const float* bk      = (const float*)d_in[3];
    const float* Wv      = (const float*)d_in[4];
    const float* bv      = (const float*)d_in[5];
    const float* Wo      = (const float*)d_in[6];
    const float* bo      = (const float*)d_in[7];
    const float* gamma   = (const float*)d_in[8];
    const float* beta    = (const float*)d_in[9];
    float* out = (float*)d_out;

    kA<<<RR, 256>>>(queries, Wk, bk);
    kB<<<dim3(SS / 256, BB), 256>>>(x);
    kC<<<BB * RR, 256>>>();
    kD<<<dim3(D_CHUNKS, BB), 256>>>(x);
    kE1<<<dim3(NH, BB), 256>>>(Wv, bv);
    kE2<<<BB, 512>>>(Wo, bo, gamma, beta, out);
}